// round 12
// baseline (speedup 1.0000x reference)
#include <cuda_runtime.h>

// Potential_6347961663538 — Gaussian form-factor splatting onto a 128x128 grid.
//
// out[b,i,j] = sum_a sum_f (ff_a·4π/ff_b)[a,f] *
//              exp(-π·(4π/ff_b)[a,f] · ((j-64-c0[b,a])² + (i-64-c1[b,a])²))
//
// π·invb = 4π²/ff_b >= 19.74, so any term with per-axis |d| > 3.5 underflows
// fp32 exp to exactly 0 — identical to the zeros the reference adds. A 7x7
// window around round(coord) reproduces every nonzero fp32 term. The dense
// B·A·P·5 = 671M-term sum collapses to 401K window terms (~1700x less work).
//
// FINAL (R12): warp-per-atom scatter — the fastest measured kernel (5.28us,
// occ 74%). 1024 blocks x 256 threads; lanes 0-4 build per-form-factor
// constants once (one divide each) and broadcast via SHFL; each lane owns
// up to 2 window pixels, computing ex2(p2_f·(dx²+dy²)) for 5 factors inline
// (raw EX2, log2e and sign pre-folded); results scattered with REDG (L2
// same-address reductions pipeline at ~0.854 cyc/lane — contention is a
// non-issue, measured in R5).
//
// Measured across 11 rounds: every kernel in the 5.3-6.7us range lands on a
// total of ~8.7us regardless of graph node count — a fixed per-replay
// harness floor (host-side graph submit). This config sits exactly on that
// floor with the fastest kernel body; further kernel cuts cannot move total.

#define SIDELEN 128
#define NATOM   2048
#define NB      4
#define NF      5
#define RAD     3
#define WIN     7
#define WPB     8            // warps per block

__device__ __forceinline__ float ex2_approx(float x) {
    float r;
    asm("ex2.approx.f32 %0, %1;" : "=f"(r) : "f"(x));
    return r;
}

__global__ void __launch_bounds__(WPB * 32) potential_scatter_kernel(
    const float* __restrict__ coords,   // [NB, NATOM, 3]
    const float* __restrict__ ff_a,     // [NATOM, NF]
    const float* __restrict__ ff_b,     // [NATOM, NF]
    float* __restrict__ out)            // [NB, SIDELEN, SIDELEN]
{
    const int warp = blockIdx.x * WPB + (threadIdx.x >> 5);  // = b*NATOM + a
    const int lane = threadIdx.x & 31;
    const int b = warp >> 11;
    const int a = warp & (NATOM - 1);

    // Lanes 0..4: one form factor each.
    //   p2   = -(4π²·log2e)/ff_b   (ex2 argument scale, sign folded)
    //   coef = ff_a·4π/ff_b
    float p2 = 0.0f, cf = 0.0f;
    if (lane < NF) {
        const float inv = __fdividef(1.0f, __ldg(&ff_b[a * NF + lane]));
        p2 = -56.9553183f * inv;
        cf = __ldg(&ff_a[a * NF + lane]) * 12.56637061f * inv;
    }
    const float p20 = __shfl_sync(0xffffffffu, p2, 0);
    const float p21 = __shfl_sync(0xffffffffu, p2, 1);
    const float p22 = __shfl_sync(0xffffffffu, p2, 2);
    const float p23 = __shfl_sync(0xffffffffu, p2, 3);
    const float p24 = __shfl_sync(0xffffffffu, p2, 4);
    const float cf0 = __shfl_sync(0xffffffffu, cf, 0);
    const float cf1 = __shfl_sync(0xffffffffu, cf, 1);
    const float cf2 = __shfl_sync(0xffffffffu, cf, 2);
    const float cf3 = __shfl_sync(0xffffffffu, cf, 3);
    const float cf4 = __shfl_sync(0xffffffffu, cf, 4);

    const float c0 = __ldg(&coords[warp * 3 + 0]);   // maps to j (fast axis)
    const float c1 = __ldg(&coords[warp * 3 + 1]);   // maps to i (slow axis)
    const int jc = __float2int_rn(c0);
    const int ic = __float2int_rn(c1);
    const float fx = (float)(jc - RAD) - c0;         // dx at window col 0
    const float fy = (float)(ic - RAD) - c1;         // dy at window row 0
    const int jb = jc + SIDELEN / 2 - RAD;
    const int ib = ic + SIDELEN / 2 - RAD;
    float* outb = out + (b << 14);

    // Two window pixels per lane: p = lane and lane+32 (49 total).
    const int wi0 = lane / WIN, wj0 = lane - wi0 * WIN;
    const int pp  = lane + 32;
    const int wi1 = pp / WIN,   wj1 = pp - wi1 * WIN;

    {
        const float dx = fx + (float)wj0, dy = fy + (float)wi0;
        const float dd = fmaf(dx, dx, dy * dy);
        float s =            cf0 * ex2_approx(p20 * dd);
        s = fmaf(cf1, ex2_approx(p21 * dd), s);
        s = fmaf(cf2, ex2_approx(p22 * dd), s);
        s = fmaf(cf3, ex2_approx(p23 * dd), s);
        s = fmaf(cf4, ex2_approx(p24 * dd), s);
        const int i = ib + wi0, j = jb + wj0;
        if ((unsigned)i < SIDELEN && (unsigned)j < SIDELEN && s != 0.0f)
            atomicAdd(&outb[(i << 7) + j], s);
    }
    if (pp < WIN * WIN) {
        const float dx = fx + (float)wj1, dy = fy + (float)wi1;
        const float dd = fmaf(dx, dx, dy * dy);
        float s =            cf0 * ex2_approx(p20 * dd);
        s = fmaf(cf1, ex2_approx(p21 * dd), s);
        s = fmaf(cf2, ex2_approx(p22 * dd), s);
        s = fmaf(cf3, ex2_approx(p23 * dd), s);
        s = fmaf(cf4, ex2_approx(p24 * dd), s);
        const int i = ib + wi1, j = jb + wj1;
        if ((unsigned)i < SIDELEN && (unsigned)j < SIDELEN && s != 0.0f)
            atomicAdd(&outb[(i << 7) + j], s);
    }
}

extern "C" void kernel_launch(void* const* d_in, const int* in_sizes, int n_in,
                              void* d_out, int out_size) {
    const float* coords = (const float*)d_in[0];
    const float* ff_a   = (const float*)d_in[1];
    const float* ff_b   = (const float*)d_in[2];
    float* out = (float*)d_out;

    cudaMemsetAsync(out, 0, (size_t)out_size * sizeof(float));
    potential_scatter_kernel<<<(NB * NATOM) / WPB, WPB * 32>>>(coords, ff_a, ff_b, out);
}

// round 13
// speedup vs baseline: 1.0264x; 1.0264x over previous
#include <cuda_runtime.h>

// Potential_6347961663538 — Gaussian form-factor splatting onto a 128x128 grid.
//
// out[b,i,j] = sum_a sum_f (ff_a·4π/ff_b)[a,f] *
//              exp(-π·(4π/ff_b)[a,f] · ((j-64-c0[b,a])² + (i-64-c1[b,a])²))
//
// ALGORITHM: π·invb = 4π²/ff_b >= 19.74 (ff_b in [0.5,2]), so any term with
// per-axis |d| > 3.5 underflows fp32 exp to exactly 0 — identical to the
// zeros the reference itself adds. A 7x7 window around round(coord) therefore
// reproduces every nonzero fp32 term: the dense B·A·P·5 = 671M-term sum
// collapses to ~401K window terms (~1700x less work).
//
// KERNEL (final, R12): warp-per-atom scatter. 1024 blocks x 256 threads
// (occ ~70%). Lanes 0-4 build per-form-factor constants once (one divide
// each: p2 = -(4π²·log2e)/ff_b with sign+log2e pre-folded for raw EX2,
// coef = ff_a·4π/ff_b) and broadcast via SHFL. Each lane owns up to 2 window
// pixels (p = lane, lane+32 of 49), computes 5x ex2(p2_f·(dx²+dy²)) inline,
// and scatters with REDG — L2 same-address reductions pipeline at ~0.854
// cyc/lane, so even the hottest central pixels (~160 adds) drain in ~140 cyc.
//
// CONVERGENCE EVIDENCE (12 rounds): totals of 8.67-8.93us for kernel times
// of 5.28-6.72us, across 1-node and 2-node graphs, with and without in-kernel
// grid barriers. The bench's per-replay submit path floors total at ~8.7us;
// GPU time below ~7us is fully hidden. This config pairs the fastest kernel
// body with the simplest structure and sits exactly on that floor.

#define SIDELEN 128
#define NATOM   2048
#define NB      4
#define NF      5
#define RAD     3
#define WIN     7
#define WPB     8            // warps per block

__device__ __forceinline__ float ex2_approx(float x) {
    float r;
    asm("ex2.approx.f32 %0, %1;" : "=f"(r) : "f"(x));
    return r;
}

__global__ void __launch_bounds__(WPB * 32) potential_scatter_kernel(
    const float* __restrict__ coords,   // [NB, NATOM, 3]
    const float* __restrict__ ff_a,     // [NATOM, NF]
    const float* __restrict__ ff_b,     // [NATOM, NF]
    float* __restrict__ out)            // [NB, SIDELEN, SIDELEN]
{
    const int warp = blockIdx.x * WPB + (threadIdx.x >> 5);  // = b*NATOM + a
    const int lane = threadIdx.x & 31;
    const int b = warp >> 11;
    const int a = warp & (NATOM - 1);

    // Lanes 0..4: one form factor each, one divide each.
    float p2 = 0.0f, cf = 0.0f;
    if (lane < NF) {
        const float inv = __fdividef(1.0f, __ldg(&ff_b[a * NF + lane]));
        p2 = -56.9553183f * inv;                      // -(4π²·log2e)/ff_b
        cf = __ldg(&ff_a[a * NF + lane]) * 12.56637061f * inv;  // ff_a·4π/ff_b
    }
    const float p20 = __shfl_sync(0xffffffffu, p2, 0);
    const float p21 = __shfl_sync(0xffffffffu, p2, 1);
    const float p22 = __shfl_sync(0xffffffffu, p2, 2);
    const float p23 = __shfl_sync(0xffffffffu, p2, 3);
    const float p24 = __shfl_sync(0xffffffffu, p2, 4);
    const float cf0 = __shfl_sync(0xffffffffu, cf, 0);
    const float cf1 = __shfl_sync(0xffffffffu, cf, 1);
    const float cf2 = __shfl_sync(0xffffffffu, cf, 2);
    const float cf3 = __shfl_sync(0xffffffffu, cf, 3);
    const float cf4 = __shfl_sync(0xffffffffu, cf, 4);

    const float c0 = __ldg(&coords[warp * 3 + 0]);   // maps to j (fast axis)
    const float c1 = __ldg(&coords[warp * 3 + 1]);   // maps to i (slow axis)
    const int jc = __float2int_rn(c0);
    const int ic = __float2int_rn(c1);
    const float fx = (float)(jc - RAD) - c0;         // dx at window col 0
    const float fy = (float)(ic - RAD) - c1;         // dy at window row 0
    const int jb = jc + SIDELEN / 2 - RAD;
    const int ib = ic + SIDELEN / 2 - RAD;
    float* outb = out + (b << 14);

    // Two window pixels per lane: p = lane and lane+32 (49 total).
    const int wi0 = lane / WIN, wj0 = lane - wi0 * WIN;
    const int pp  = lane + 32;
    const int wi1 = pp / WIN,   wj1 = pp - wi1 * WIN;

    {
        const float dx = fx + (float)wj0, dy = fy + (float)wi0;
        const float dd = fmaf(dx, dx, dy * dy);
        float s =            cf0 * ex2_approx(p20 * dd);
        s = fmaf(cf1, ex2_approx(p21 * dd), s);
        s = fmaf(cf2, ex2_approx(p22 * dd), s);
        s = fmaf(cf3, ex2_approx(p23 * dd), s);
        s = fmaf(cf4, ex2_approx(p24 * dd), s);
        const int i = ib + wi0, j = jb + wj0;
        if ((unsigned)i < SIDELEN && (unsigned)j < SIDELEN && s != 0.0f)
            atomicAdd(&outb[(i << 7) + j], s);
    }
    if (pp < WIN * WIN) {
        const float dx = fx + (float)wj1, dy = fy + (float)wi1;
        const float dd = fmaf(dx, dx, dy * dy);
        float s =            cf0 * ex2_approx(p20 * dd);
        s = fmaf(cf1, ex2_approx(p21 * dd), s);
        s = fmaf(cf2, ex2_approx(p22 * dd), s);
        s = fmaf(cf3, ex2_approx(p23 * dd), s);
        s = fmaf(cf4, ex2_approx(p24 * dd), s);
        const int i = ib + wi1, j = jb + wj1;
        if ((unsigned)i < SIDELEN && (unsigned)j < SIDELEN && s != 0.0f)
            atomicAdd(&outb[(i << 7) + j], s);
    }
}

extern "C" void kernel_launch(void* const* d_in, const int* in_sizes, int n_in,
                              void* d_out, int out_size) {
    const float* coords = (const float*)d_in[0];
    const float* ff_a   = (const float*)d_in[1];
    const float* ff_b   = (const float*)d_in[2];
    float* out = (float*)d_out;

    cudaMemsetAsync(out, 0, (size_t)out_size * sizeof(float));
    potential_scatter_kernel<<<(NB * NATOM) / WPB, WPB * 32>>>(coords, ff_a, ff_b, out);
}